// round 9
// baseline (speedup 1.0000x reference)
#include <cuda_runtime.h>
#include <cstdint>

#define N_NODES 100000
#define N_EDGES 1600000
#define HID     128
#define NH      12800000      // N_NODES * HID
#define NB_SCAN 391           // ceil(N_NODES/256)
#define WSTRIDE 136           // smem W row stride (u32 words) -> conflict-free frags

// ---------------- scratch (__device__ globals: no runtime allocation) -------
__device__ float g_dinv[N_NODES];
__device__ int   g_cnt[N_NODES];
__device__ int   g_rowptr[N_NODES + 1];
__device__ int   g_cursor[N_NODES];
__device__ int2  g_ecc[N_EDGES];          // (src, coef-as-int) interleaved
__device__ int   g_bsum[512];
__device__ int   g_boff[512];
__device__ float g_agg[NH];               // P1 / agg2 buffer
__device__ float g_h1[NH];
__device__ float g_mu[NH];
__device__ float g_lv[NH];

// ---------------- degree / norm ---------------------------------------------
__global__ void k_zero_cnt() {
    int i = blockIdx.x * 256 + threadIdx.x;
    if (i < N_NODES) g_cnt[i] = 0;
}
__global__ void k_degree(const int* __restrict__ dst) {
    int i = blockIdx.x * 256 + threadIdx.x;
    if (i < N_EDGES) atomicAdd(&g_cnt[dst[i]], 1);
}
__global__ void k_dinv() {
    int i = blockIdx.x * 256 + threadIdx.x;
    if (i < N_NODES) g_dinv[i] = rsqrtf((float)g_cnt[i] + 1.0f);
}

// ---------------- CSR build: block scan + fixup ------------------------------
__global__ void k_scan1() {
    __shared__ int sh[256];
    int tid = threadIdx.x;
    int i = blockIdx.x * 256 + tid;
    int v = (i < N_NODES) ? g_cnt[i] : 0;
    sh[tid] = v;
    __syncthreads();
#pragma unroll
    for (int off = 1; off < 256; off <<= 1) {
        int t = (tid >= off) ? sh[tid - off] : 0;
        __syncthreads();
        sh[tid] += t;
        __syncthreads();
    }
    if (i < N_NODES) g_rowptr[i] = sh[tid] - v;
    if (tid == 255) g_bsum[blockIdx.x] = sh[255];
}
__global__ void k_scan2() {
    __shared__ int sh[512];
    int tid = threadIdx.x;
    int v = (tid < NB_SCAN) ? g_bsum[tid] : 0;
    sh[tid] = v;
    __syncthreads();
#pragma unroll
    for (int off = 1; off < 512; off <<= 1) {
        int t = (tid >= off) ? sh[tid - off] : 0;
        __syncthreads();
        sh[tid] += t;
        __syncthreads();
    }
    g_boff[tid] = sh[tid] - v;
    if (tid == 0) g_rowptr[N_NODES] = N_EDGES;
}
__global__ void k_scan3() {
    int i = blockIdx.x * 256 + threadIdx.x;
    if (i < N_NODES) {
        int r = g_rowptr[i] + g_boff[i >> 8];
        g_rowptr[i] = r;
        g_cursor[i] = r;
    }
}
__global__ void k_fill(const int* __restrict__ src, const int* __restrict__ dst) {
    int e = blockIdx.x * 256 + threadIdx.x;
    if (e >= N_EDGES) return;
    int d = dst[e], s = src[e];
    int pos = atomicAdd(&g_cursor[d], 1);
    float c = g_dinv[s] * g_dinv[d];
    g_ecc[pos] = make_int2(s, __float_as_int(c));
}

// ---------------- CSR aggregation: out = A_norm @ feat  (+opt bias/ELU) -----
__global__ __launch_bounds__(256) void k_agg(const float* __restrict__ feat,
                                             float* __restrict__ outp,
                                             const float* __restrict__ bias,
                                             int act) {
    int gw   = (blockIdx.x * 256 + threadIdx.x) >> 5;
    int node = gw >> 1;
    int half = gw & 1;
    int lane = threadIdx.x & 31;
    if (node >= N_NODES) return;

    int beg = g_rowptr[node];
    int end = g_rowptr[node + 1];
    float di = g_dinv[node];
    float sc = di * di;

    const float2* fp = (const float2*)feat;
    int off = half * 32 + lane;

    float2 acc = fp[(size_t)node * 64 + off];
    acc.x *= sc; acc.y *= sc;

    int j = beg;
    for (; j + 8 <= end; j += 8) {
        int2 m[8];
#pragma unroll
        for (int q = 0; q < 8; q++) m[q] = g_ecc[j + q];
        float2 v[8];
#pragma unroll
        for (int q = 0; q < 8; q++)
            v[q] = fp[(size_t)m[q].x * 64 + off];
#pragma unroll
        for (int q = 0; q < 8; q++) {
            float c = __int_as_float(m[q].y);
            acc.x = fmaf(c, v[q].x, acc.x);
            acc.y = fmaf(c, v[q].y, acc.y);
        }
    }
    for (; j + 2 <= end; j += 2) {
        int2 m0 = g_ecc[j], m1 = g_ecc[j + 1];
        float2 v0 = fp[(size_t)m0.x * 64 + off];
        float2 v1 = fp[(size_t)m1.x * 64 + off];
        float c0 = __int_as_float(m0.y), c1 = __int_as_float(m1.y);
        acc.x = fmaf(c0, v0.x, acc.x); acc.y = fmaf(c0, v0.y, acc.y);
        acc.x = fmaf(c1, v1.x, acc.x); acc.y = fmaf(c1, v1.y, acc.y);
    }
    if (j < end) {
        int2 m0 = g_ecc[j];
        float2 v0 = fp[(size_t)m0.x * 64 + off];
        float c0 = __int_as_float(m0.y);
        acc.x = fmaf(c0, v0.x, acc.x); acc.y = fmaf(c0, v0.y, acc.y);
    }
    if (bias) {
        float2 b = ((const float2*)bias)[off];
        acc.x += b.x; acc.y += b.y;
    }
    if (act) {
        acc.x = (acc.x > 0.f) ? acc.x : expm1f(acc.x);
        acc.y = (acc.y > 0.f) ? acc.y : expm1f(acc.y);
    }
    ((float2*)outp)[(size_t)node * 64 + off] = acc;
}

// ------- JAX-exact RNG: PARTITIONABLE threefry2x32 + XLA erfinv -------------
__device__ __forceinline__ uint32_t rotl32(uint32_t x, int d) {
    return (x << d) | (x >> (32 - d));
}
__device__ __forceinline__ uint32_t threefry_bits_0_42(uint32_t x0, uint32_t x1) {
    const uint32_t k0 = 0u, k1 = 42u;
    const uint32_t k2 = k0 ^ k1 ^ 0x1BD11BDAu;
    x0 += k0; x1 += k1;
#define TF_RND(r) { x0 += x1; x1 = rotl32(x1, r); x1 ^= x0; }
    TF_RND(13) TF_RND(15) TF_RND(26) TF_RND(6)
    x0 += k1; x1 += k2 + 1u;
    TF_RND(17) TF_RND(29) TF_RND(16) TF_RND(24)
    x0 += k2; x1 += k0 + 2u;
    TF_RND(13) TF_RND(15) TF_RND(26) TF_RND(6)
    x0 += k0; x1 += k1 + 3u;
    TF_RND(17) TF_RND(29) TF_RND(16) TF_RND(24)
    x0 += k1; x1 += k2 + 4u;
    TF_RND(13) TF_RND(15) TF_RND(26) TF_RND(6)
    x0 += k2; x1 += k0 + 5u;
#undef TF_RND
    return x0 ^ x1;
}
__device__ __forceinline__ float erfinv_xla(float x) {
    float w = -log1pf(-x * x);
    float p;
    if (w < 5.0f) {
        w -= 2.5f;
        p = 2.81022636e-08f;
        p = fmaf(p, w, 3.43273939e-07f);
        p = fmaf(p, w, -3.5233877e-06f);
        p = fmaf(p, w, -4.39150654e-06f);
        p = fmaf(p, w, 0.00021858087f);
        p = fmaf(p, w, -0.00125372503f);
        p = fmaf(p, w, -0.00417768164f);
        p = fmaf(p, w, 0.246640727f);
        p = fmaf(p, w, 1.50140941f);
    } else {
        w = sqrtf(w) - 3.0f;
        p = -0.000200214257f;
        p = fmaf(p, w, 0.000100950558f);
        p = fmaf(p, w, 0.00134934322f);
        p = fmaf(p, w, -0.00367342844f);
        p = fmaf(p, w, 0.00573950773f);
        p = fmaf(p, w, -0.0076224613f);
        p = fmaf(p, w, 0.00943887047f);
        p = fmaf(p, w, 1.00167406f);
        p = fmaf(p, w, 2.83297682f);
    }
    return p * x;
}
__device__ __forceinline__ float bits_to_normal(uint32_t bits) {
    float u01 = __uint_as_float((bits >> 9) | 0x3f800000u) - 1.0f;
    const float lo = -0.99999994f;
    float u = fmaf(u01, 2.0f, lo);
    u = fmaxf(u, lo);
    return 1.41421356237f * erfinv_xla(u);
}

// ---------------- tf32 tensor-core GEMM with 3-term precision split ---------
// C[M,128] = A[M,128] @ W[128,128] (+bias)(+ELU)(+mirror)(+reparam)
// block: 128 rows, 8 warps; warp = 16 rows x 128 cols.
// smem: W_hi + W_lo as tf32 (u32), row stride 136 (bank-conflict-free frags).
#define GF_BIAS 1
#define GF_ELU  2
#define GF_REP  4

__device__ __forceinline__ uint32_t f2tf32(float f) {
    uint32_t u;
    asm("cvt.rna.tf32.f32 %0, %1;" : "=r"(u) : "f"(f));
    return u;
}
__device__ __forceinline__ void mma_tf32(float d[4], uint32_t a0, uint32_t a1,
                                         uint32_t a2, uint32_t a3,
                                         uint32_t b0, uint32_t b1) {
    asm volatile("mma.sync.aligned.m16n8k8.row.col.f32.tf32.tf32.f32 "
                 "{%0,%1,%2,%3}, {%4,%5,%6,%7}, {%8,%9}, {%0,%1,%2,%3};"
                 : "+f"(d[0]), "+f"(d[1]), "+f"(d[2]), "+f"(d[3])
                 : "r"(a0), "r"(a1), "r"(a2), "r"(a3), "r"(b0), "r"(b1));
}

__global__ __launch_bounds__(256) void k_mma(const float* __restrict__ A,
                                             const float* __restrict__ W,
                                             const float* __restrict__ bias,
                                             float* __restrict__ C,
                                             float* __restrict__ mirror,
                                             const float* __restrict__ mu_in,
                                             float* __restrict__ z_out,
                                             int flags) {
    extern __shared__ uint32_t smw[];
    uint32_t* whi = smw;                      // [128][WSTRIDE]
    uint32_t* wlo = smw + 128 * WSTRIDE;

    int tid  = threadIdx.x;
    int warp = tid >> 5;
    int lane = tid & 31;
    int gid  = lane >> 2;                     // 0..7
    int tig  = lane & 3;                      // 0..3

    // load + split W into smem
    for (int i = tid; i < 128 * 128; i += 256) {
        int k = i >> 7, n = i & 127;
        float w = W[i];
        uint32_t hi = f2tf32(w);
        float lof = w - __uint_as_float(hi);
        whi[k * WSTRIDE + n] = hi;
        wlo[k * WSTRIDE + n] = f2tf32(lof);
    }
    __syncthreads();

    int row0 = blockIdx.x << 7;
    int r1 = row0 + warp * 16 + gid;          // fragment rows
    int r2 = r1 + 8;
    bool v1 = (r1 < N_NODES), v2 = (r2 < N_NODES);

    float d[16][4];
#pragma unroll
    for (int nn = 0; nn < 16; nn++)
#pragma unroll
        for (int q = 0; q < 4; q++) d[nn][q] = 0.f;

    const float* A1 = A + (size_t)r1 * HID;
    const float* A2 = A + (size_t)r2 * HID;

    for (int kk = 0; kk < 16; kk++) {
        int c0 = kk * 8 + tig;
        float a0f = v1 ? A1[c0]     : 0.f;
        float a1f = v2 ? A2[c0]     : 0.f;
        float a2f = v1 ? A1[c0 + 4] : 0.f;
        float a3f = v2 ? A2[c0 + 4] : 0.f;
        uint32_t a0h = f2tf32(a0f), a1h = f2tf32(a1f);
        uint32_t a2h = f2tf32(a2f), a3h = f2tf32(a3f);
        uint32_t a0l = f2tf32(a0f - __uint_as_float(a0h));
        uint32_t a1l = f2tf32(a1f - __uint_as_float(a1h));
        uint32_t a2l = f2tf32(a2f - __uint_as_float(a2h));
        uint32_t a3l = f2tf32(a3f - __uint_as_float(a3h));

        int kb0 = (kk * 8 + tig) * WSTRIDE + gid;      // b0 row = tig
        int kb1 = kb0 + 4 * WSTRIDE;                   // b1 row = tig+4
#pragma unroll
        for (int nn = 0; nn < 16; nn++) {
            uint32_t b0h = whi[kb0 + nn * 8];
            uint32_t b1h = whi[kb1 + nn * 8];
            uint32_t b0l = wlo[kb0 + nn * 8];
            uint32_t b1l = wlo[kb1 + nn * 8];
            mma_tf32(d[nn], a0h, a1h, a2h, a3h, b0h, b1h);   // hi*hi
            mma_tf32(d[nn], a0h, a1h, a2h, a3h, b0l, b1l);   // hi*lo
            mma_tf32(d[nn], a0l, a1l, a2l, a3l, b0h, b1h);   // lo*hi
        }
    }

    // epilogue: lane owns cols nn*8 + 2*tig (+1), rows r1 / r2
#pragma unroll
    for (int nn = 0; nn < 16; nn++) {
        int col = nn * 8 + 2 * tig;
        float bx = 0.f, by = 0.f;
        if (flags & GF_BIAS) {
            float2 b = *(const float2*)(bias + col);
            bx = b.x; by = b.y;
        }
#pragma unroll
        for (int e = 0; e < 2; e++) {
            int r = e ? r2 : r1;
            if (e ? !v2 : !v1) continue;
            float vx = d[nn][2 * e + 0] + bx;
            float vy = d[nn][2 * e + 1] + by;
            if (flags & GF_ELU) {
                vx = (vx > 0.f) ? vx : expm1f(vx);
                vy = (vy > 0.f) ? vy : expm1f(vy);
            }
            size_t base = (size_t)r * HID + col;
            *(float2*)(C + base) = make_float2(vx, vy);
            if (mirror) *(float2*)(mirror + base) = make_float2(vx, vy);
            if (flags & GF_REP) {
                float ex = bits_to_normal(threefry_bits_0_42(0u, (uint32_t)base));
                float ey = bits_to_normal(threefry_bits_0_42(0u, (uint32_t)base + 1));
                float zx = mu_in[base]     + ex * expf(0.5f * vx);
                float zy = mu_in[base + 1] + ey * expf(0.5f * vy);
                *(float2*)(z_out + base) = make_float2(zx, zy);
            }
        }
    }
}

// ---------------- launch -----------------------------------------------------
extern "C" void kernel_launch(void* const* d_in, const int* in_sizes, int n_in,
                              void* d_out, int out_size) {
    const float* x   = (const float*)d_in[0];
    const int*   ei  = (const int*)d_in[1];
    const float* W1  = (const float*)d_in[2];
    const float* b1  = (const float*)d_in[3];
    const float* Wmu = (const float*)d_in[4];
    const float* bmu = (const float*)d_in[5];
    const float* Wlv = (const float*)d_in[6];
    const float* blv = (const float*)d_in[7];
    float* out = (float*)d_out;

    const int* src = ei;
    const int* dst = ei + N_EDGES;

    void *p_agg, *p_h1, *p_mu, *p_lv;
    cudaGetSymbolAddress(&p_agg, g_agg);
    cudaGetSymbolAddress(&p_h1,  g_h1);
    cudaGetSymbolAddress(&p_mu,  g_mu);
    cudaGetSymbolAddress(&p_lv,  g_lv);

    int big = (out_size >= 3 * NH);
    float* mu_mirror = big ? (out + NH)     : nullptr;
    float* lv_dst    = big ? (out + 2 * NH) : (float*)p_lv;

    const size_t mma_smem = 2 * 128 * WSTRIDE * sizeof(uint32_t);  // 139,264 B
    cudaFuncSetAttribute(k_mma, cudaFuncAttributeMaxDynamicSharedMemorySize,
                         (int)mma_smem);

    const int nb_nodes = (N_NODES + 255) / 256;      // 391
    const int nb_edges = (N_EDGES + 255) / 256;      // 6250
    const int nb_agg   = (N_NODES * 64 + 255) / 256; // 25000
    const int nb_mma   = (N_NODES + 127) / 128;      // 782

    // idx 0-2: degree prep
    k_zero_cnt<<<nb_nodes, 256>>>();
    k_degree<<<nb_edges, 256>>>(dst);
    k_dinv<<<nb_nodes, 256>>>();

    // idx 3 (PROFILED): P1 = X @ W1  (bias/ELU deferred to agg epilogue)
    k_mma<<<nb_mma, 256, mma_smem>>>(x, W1, nullptr, (float*)p_agg,
                                     nullptr, nullptr, nullptr, 0);

    // idx 4-7: CSR build
    k_scan1<<<nb_nodes, 256>>>();
    k_scan2<<<1, 512>>>();
    k_scan3<<<nb_nodes, 256>>>();
    k_fill<<<nb_edges, 256>>>(src, dst);

    // idx 8: h1 = elu(A_norm @ P1 + b1)
    k_agg<<<nb_agg, 256>>>((const float*)p_agg, (float*)p_h1, b1, 1);

    // idx 9: agg2 = A_norm @ h1
    k_agg<<<nb_agg, 256>>>((const float*)p_h1, (float*)p_agg, nullptr, 0);

    // idx 10: mu = agg2 @ Wmu + bmu  (scratch + mirrored to out)
    k_mma<<<nb_mma, 256, mma_smem>>>((const float*)p_agg, Wmu, bmu,
                                     (float*)p_mu, mu_mirror,
                                     nullptr, nullptr, GF_BIAS);

    // idx 11: lv = agg2 @ Wlv + blv ; z = mu + eps*exp(0.5*lv)
    k_mma<<<nb_mma, 256, mma_smem>>>((const float*)p_agg, Wlv, blv,
                                     lv_dst, nullptr,
                                     (const float*)p_mu, out,
                                     GF_BIAS | GF_REP);
}

// round 12
// speedup vs baseline: 1.0544x; 1.0544x over previous
#include <cuda_runtime.h>
#include <cuda_bf16.h>
#include <cstdint>

#define N_NODES 100000
#define N_EDGES 1600000
#define HID     128
#define NH      12800000      // N_NODES * HID
#define NB_SCAN 391           // ceil(N_NODES/256)

// ---------------- scratch (__device__ globals: no runtime allocation) -------
__device__ float g_dinv[N_NODES];
__device__ int   g_cnt[N_NODES];          // zeroed at startup + by k_scan3 each replay
__device__ int   g_rowptr[N_NODES + 1];
__device__ int   g_cursor[N_NODES];
__device__ int2  g_ecc[N_EDGES];          // (src, coef-as-int) interleaved
__device__ int   g_bsum[512];
__device__ int   g_boff[512];
__device__ uint4 g_wfrag[3 * 4096];       // pre-packed bf16 hi/lo MMA fragments
__device__ float g_agg[NH];               // P1 / agg2 buffer
__device__ float g_h1[NH];
__device__ float g_mu[NH];
__device__ float g_lv[NH];

// ---------------- bf16 split helper ------------------------------------------
__device__ __forceinline__ void split2(float2 f, uint32_t& hi, uint32_t& lo) {
    __nv_bfloat162 h = __float22bfloat162_rn(f);
    float2 hf = __bfloat1622float2(h);
    __nv_bfloat162 l = __float22bfloat162_rn(make_float2(f.x - hf.x, f.y - hf.y));
    hi = *reinterpret_cast<uint32_t*>(&h);
    lo = *reinterpret_cast<uint32_t*>(&l);
}

// ---------------- W fragment prepack (one launch, all 3 matrices) ------------
// fragment entry e=(kk,nn,lane): lane t=lane%4,c=lane/4; n=nn*8+c; k0=kk*16+2t
// uint4 = {b0_hi, b1_hi, b0_lo, b1_lo}; b0 covers k0,k0+1; b1 covers k0+8,k0+9
__global__ void k_wprep(const float* __restrict__ W1,
                        const float* __restrict__ Wmu,
                        const float* __restrict__ Wlv) {
    int e = blockIdx.x * 256 + threadIdx.x;
    if (e >= 3 * 4096) return;
    int m = e >> 12;
    const float* W = (m == 0) ? W1 : ((m == 1) ? Wmu : Wlv);
    int f    = e & 4095;
    int lane = f & 31;
    int nn   = (f >> 5) & 15;
    int kk   = f >> 9;
    int t = lane & 3, c = lane >> 2;
    int n  = nn * 8 + c;
    int k0 = kk * 16 + 2 * t;
    float w00 = W[(k0    ) * HID + n], w01 = W[(k0 + 1) * HID + n];
    float w10 = W[(k0 + 8) * HID + n], w11 = W[(k0 + 9) * HID + n];
    uint32_t h0, l0, h1, l1;
    split2(make_float2(w00, w01), h0, l0);
    split2(make_float2(w10, w11), h1, l1);
    g_wfrag[e] = make_uint4(h0, h1, l0, l1);
}

// ---------------- degree ------------------------------------------------------
__global__ void k_degree(const int* __restrict__ dst) {
    int i = blockIdx.x * 256 + threadIdx.x;
    if (i < N_EDGES) atomicAdd(&g_cnt[dst[i]], 1);
}

// ---------------- CSR build: block scan (+dinv) + fixup (+cnt re-zero) -------
__global__ void k_scan1() {
    __shared__ int sh[256];
    int tid = threadIdx.x;
    int i = blockIdx.x * 256 + tid;
    int v = (i < N_NODES) ? g_cnt[i] : 0;
    sh[tid] = v;
    __syncthreads();
#pragma unroll
    for (int off = 1; off < 256; off <<= 1) {
        int t = (tid >= off) ? sh[tid - off] : 0;
        __syncthreads();
        sh[tid] += t;
        __syncthreads();
    }
    if (i < N_NODES) {
        g_rowptr[i] = sh[tid] - v;
        g_dinv[i]   = rsqrtf((float)v + 1.0f);
    }
    if (tid == 255) g_bsum[blockIdx.x] = sh[255];
}
__global__ void k_scan2() {
    __shared__ int sh[512];
    int tid = threadIdx.x;
    int v = (tid < NB_SCAN) ? g_bsum[tid] : 0;
    sh[tid] = v;
    __syncthreads();
#pragma unroll
    for (int off = 1; off < 512; off <<= 1) {
        int t = (tid >= off) ? sh[tid - off] : 0;
        __syncthreads();
        sh[tid] += t;
        __syncthreads();
    }
    g_boff[tid] = sh[tid] - v;
    if (tid == 0) g_rowptr[N_NODES] = N_EDGES;
}
__global__ void k_scan3() {
    int i = blockIdx.x * 256 + threadIdx.x;
    if (i < N_NODES) {
        int r = g_rowptr[i] + g_boff[i >> 8];
        g_rowptr[i] = r;
        g_cursor[i] = r;
        g_cnt[i]    = 0;           // ready for next replay
    }
}
__global__ void k_fill(const int* __restrict__ src, const int* __restrict__ dst) {
    int e = blockIdx.x * 256 + threadIdx.x;
    if (e >= N_EDGES) return;
    int d = dst[e], s = src[e];
    int pos = atomicAdd(&g_cursor[d], 1);
    float c = g_dinv[s] * g_dinv[d];
    g_ecc[pos] = make_int2(s, __float_as_int(c));
}

// ---------------- CSR aggregation: out = A_norm @ feat  (+opt bias/ELU) -----
__global__ __launch_bounds__(256) void k_agg(const float* __restrict__ feat,
                                             float* __restrict__ outp,
                                             const float* __restrict__ bias,
                                             int act) {
    int gw   = (blockIdx.x * 256 + threadIdx.x) >> 5;
    int node = gw >> 1;
    int half = gw & 1;
    int lane = threadIdx.x & 31;
    if (node >= N_NODES) return;

    int beg = g_rowptr[node];
    int end = g_rowptr[node + 1];
    float di = g_dinv[node];
    float sc = di * di;

    const float2* fp = (const float2*)feat;
    int off = half * 32 + lane;

    float2 acc = fp[(size_t)node * 64 + off];
    acc.x *= sc; acc.y *= sc;

    int j = beg;
    for (; j + 8 <= end; j += 8) {
        int2 m[8];
#pragma unroll
        for (int q = 0; q < 8; q++) m[q] = g_ecc[j + q];
        float2 v[8];
#pragma unroll
        for (int q = 0; q < 8; q++)
            v[q] = fp[(size_t)m[q].x * 64 + off];
#pragma unroll
        for (int q = 0; q < 8; q++) {
            float c = __int_as_float(m[q].y);
            acc.x = fmaf(c, v[q].x, acc.x);
            acc.y = fmaf(c, v[q].y, acc.y);
        }
    }
    for (; j + 2 <= end; j += 2) {
        int2 m0 = g_ecc[j], m1 = g_ecc[j + 1];
        float2 v0 = fp[(size_t)m0.x * 64 + off];
        float2 v1 = fp[(size_t)m1.x * 64 + off];
        float c0 = __int_as_float(m0.y), c1 = __int_as_float(m1.y);
        acc.x = fmaf(c0, v0.x, acc.x); acc.y = fmaf(c0, v0.y, acc.y);
        acc.x = fmaf(c1, v1.x, acc.x); acc.y = fmaf(c1, v1.y, acc.y);
    }
    if (j < end) {
        int2 m0 = g_ecc[j];
        float2 v0 = fp[(size_t)m0.x * 64 + off];
        float c0 = __int_as_float(m0.y);
        acc.x = fmaf(c0, v0.x, acc.x); acc.y = fmaf(c0, v0.y, acc.y);
    }
    if (bias) {
        float2 b = ((const float2*)bias)[off];
        acc.x += b.x; acc.y += b.y;
    }
    if (act) {
        acc.x = (acc.x > 0.f) ? acc.x : expm1f(acc.x);
        acc.y = (acc.y > 0.f) ? acc.y : expm1f(acc.y);
    }
    ((float2*)outp)[(size_t)node * 64 + off] = acc;
}

// ------- JAX-exact RNG: PARTITIONABLE threefry2x32 + XLA erfinv -------------
__device__ __forceinline__ uint32_t rotl32(uint32_t x, int d) {
    return (x << d) | (x >> (32 - d));
}
__device__ __forceinline__ uint32_t threefry_bits_0_42(uint32_t x0, uint32_t x1) {
    const uint32_t k0 = 0u, k1 = 42u;
    const uint32_t k2 = k0 ^ k1 ^ 0x1BD11BDAu;
    x0 += k0; x1 += k1;
#define TF_RND(r) { x0 += x1; x1 = rotl32(x1, r); x1 ^= x0; }
    TF_RND(13) TF_RND(15) TF_RND(26) TF_RND(6)
    x0 += k1; x1 += k2 + 1u;
    TF_RND(17) TF_RND(29) TF_RND(16) TF_RND(24)
    x0 += k2; x1 += k0 + 2u;
    TF_RND(13) TF_RND(15) TF_RND(26) TF_RND(6)
    x0 += k0; x1 += k1 + 3u;
    TF_RND(17) TF_RND(29) TF_RND(16) TF_RND(24)
    x0 += k1; x1 += k2 + 4u;
    TF_RND(13) TF_RND(15) TF_RND(26) TF_RND(6)
    x0 += k2; x1 += k0 + 5u;
#undef TF_RND
    return x0 ^ x1;
}
__device__ __forceinline__ float erfinv_xla(float x) {
    float w = -log1pf(-x * x);
    float p;
    if (w < 5.0f) {
        w -= 2.5f;
        p = 2.81022636e-08f;
        p = fmaf(p, w, 3.43273939e-07f);
        p = fmaf(p, w, -3.5233877e-06f);
        p = fmaf(p, w, -4.39150654e-06f);
        p = fmaf(p, w, 0.00021858087f);
        p = fmaf(p, w, -0.00125372503f);
        p = fmaf(p, w, -0.00417768164f);
        p = fmaf(p, w, 0.246640727f);
        p = fmaf(p, w, 1.50140941f);
    } else {
        w = sqrtf(w) - 3.0f;
        p = -0.000200214257f;
        p = fmaf(p, w, 0.000100950558f);
        p = fmaf(p, w, 0.00134934322f);
        p = fmaf(p, w, -0.00367342844f);
        p = fmaf(p, w, 0.00573950773f);
        p = fmaf(p, w, -0.0076224613f);
        p = fmaf(p, w, 0.00943887047f);
        p = fmaf(p, w, 1.00167406f);
        p = fmaf(p, w, 2.83297682f);
    }
    return p * x;
}
__device__ __forceinline__ float bits_to_normal(uint32_t bits) {
    float u01 = __uint_as_float((bits >> 9) | 0x3f800000u) - 1.0f;
    const float lo = -0.99999994f;
    float u = fmaf(u01, 2.0f, lo);
    u = fmaxf(u, lo);
    return 1.41421356237f * erfinv_xla(u);
}

// ---------------- bf16 tensor-core GEMM, 3-term split, prepacked W ----------
// C[M,128] = A[M,128] @ W[128,128] (+bias)(+ELU)(+mirror)(+reparam)
// 8 warps x 16 rows = 128 rows/block; smem = 64KB fragments -> 2 CTAs/SM.
#define GF_BIAS 1
#define GF_ELU  2
#define GF_REP  4

__device__ __forceinline__ void mma_bf16(float d[4], uint32_t a0, uint32_t a1,
                                         uint32_t a2, uint32_t a3,
                                         uint32_t b0, uint32_t b1) {
    asm volatile("mma.sync.aligned.m16n8k16.row.col.f32.bf16.bf16.f32 "
                 "{%0,%1,%2,%3}, {%4,%5,%6,%7}, {%8,%9}, {%0,%1,%2,%3};"
                 : "+f"(d[0]), "+f"(d[1]), "+f"(d[2]), "+f"(d[3])
                 : "r"(a0), "r"(a1), "r"(a2), "r"(a3), "r"(b0), "r"(b1));
}

__global__ __launch_bounds__(256, 2) void k_mma(const float* __restrict__ A,
                                                const uint4* __restrict__ wf,
                                                const float* __restrict__ bias,
                                                float* __restrict__ C,
                                                float* __restrict__ mirror,
                                                const float* __restrict__ mu_in,
                                                float* __restrict__ z_out,
                                                int flags) {
    extern __shared__ uint4 sw[];               // 4096 fragment entries (64 KB)
    int tid  = threadIdx.x;
    int warp = tid >> 5;
    int lane = tid & 31;
    int t = lane & 3, g = lane >> 2;

    // coalesced fragment copy gmem -> smem
#pragma unroll
    for (int i = 0; i < 16; i++) sw[tid + i * 256] = wf[tid + i * 256];
    __syncthreads();

    int row0 = blockIdx.x << 7;
    int r1 = row0 + warp * 16 + g;
    int r2 = r1 + 8;
    bool v1 = (r1 < N_NODES), v2 = (r2 < N_NODES);
    const float* A1 = A + (size_t)r1 * HID;
    const float* A2 = A + (size_t)r2 * HID;

    float d[16][4];
#pragma unroll
    for (int nn = 0; nn < 16; nn++)
#pragma unroll
        for (int q = 0; q < 4; q++) d[nn][q] = 0.f;

    const float2 z2 = make_float2(0.f, 0.f);

#pragma unroll
    for (int kk = 0; kk < 8; kk++) {
        int kc = kk * 16 + 2 * t;
        float2 f0 = v1 ? *(const float2*)(A1 + kc)     : z2;   // r1, k kc..kc+1
        float2 f2 = v1 ? *(const float2*)(A1 + kc + 8) : z2;   // r1, k kc+8..kc+9
        float2 f1 = v2 ? *(const float2*)(A2 + kc)     : z2;   // r2 low
        float2 f3 = v2 ? *(const float2*)(A2 + kc + 8) : z2;   // r2 high
        uint32_t a0h, a0l, a1h, a1l, a2h, a2l, a3h, a3l;
        split2(f0, a0h, a0l);
        split2(f1, a1h, a1l);
        split2(f2, a2h, a2l);
        split2(f3, a3h, a3l);

        const uint4* base = sw + (kk << 9) + lane;     // kk*16*32 + lane
#pragma unroll
        for (int nn = 0; nn < 16; nn++) {
            uint4 b = base[nn << 5];                   // LDS.128, conflict-free
            mma_bf16(d[nn], a0h, a1h, a2h, a3h, b.x, b.y);   // hi*hi
            mma_bf16(d[nn], a0h, a1h, a2h, a3h, b.z, b.w);   // hi*lo
            mma_bf16(d[nn], a0l, a1l, a2l, a3l, b.x, b.y);   // lo*hi
        }
    }

    // epilogue: lane owns cols nn*8 + 2t (+1), rows r1 (c0,c1) / r2 (c2,c3)
#pragma unroll
    for (int nn = 0; nn < 16; nn++) {
        int col = nn * 8 + 2 * t;
        float bx = 0.f, by = 0.f;
        if (flags & GF_BIAS) {
            float2 b = *(const float2*)(bias + col);
            bx = b.x; by = b.y;
        }
#pragma unroll
        for (int e = 0; e < 2; e++) {
            int r = e ? r2 : r1;
            if (e ? !v2 : !v1) continue;
            float vx = d[nn][2 * e + 0] + bx;
            float vy = d[nn][2 * e + 1] + by;
            if (flags & GF_ELU) {
                vx = (vx > 0.f) ? vx : expm1f(vx);
                vy = (vy > 0.f) ? vy : expm1f(vy);
            }
            size_t base2 = (size_t)r * HID + col;
            *(float2*)(C + base2) = make_float2(vx, vy);
            if (mirror) *(float2*)(mirror + base2) = make_float2(vx, vy);
            if (flags & GF_REP) {
                float ex = bits_to_normal(threefry_bits_0_42(0u, (uint32_t)base2));
                float ey = bits_to_normal(threefry_bits_0_42(0u, (uint32_t)base2 + 1));
                float zx = mu_in[base2]     + ex * expf(0.5f * vx);
                float zy = mu_in[base2 + 1] + ey * expf(0.5f * vy);
                *(float2*)(z_out + base2) = make_float2(zx, zy);
            }
        }
    }
}

// ---------------- launch -----------------------------------------------------
extern "C" void kernel_launch(void* const* d_in, const int* in_sizes, int n_in,
                              void* d_out, int out_size) {
    const float* x   = (const float*)d_in[0];
    const int*   ei  = (const int*)d_in[1];
    const float* W1  = (const float*)d_in[2];
    const float* b1  = (const float*)d_in[3];
    const float* Wmu = (const float*)d_in[4];
    const float* bmu = (const float*)d_in[5];
    const float* Wlv = (const float*)d_in[6];
    const float* blv = (const float*)d_in[7];
    float* out = (float*)d_out;

    const int* src = ei;
    const int* dst = ei + N_EDGES;

    void *p_agg, *p_h1, *p_mu, *p_lv, *p_wf;
    cudaGetSymbolAddress(&p_agg, g_agg);
    cudaGetSymbolAddress(&p_h1,  g_h1);
    cudaGetSymbolAddress(&p_mu,  g_mu);
    cudaGetSymbolAddress(&p_lv,  g_lv);
    cudaGetSymbolAddress(&p_wf,  g_wfrag);
    const uint4* wf = (const uint4*)p_wf;

    int big = (out_size >= 3 * NH);
    float* mu_mirror = big ? (out + NH)     : nullptr;
    float* lv_dst    = big ? (out + 2 * NH) : (float*)p_lv;

    const size_t mma_smem = 4096 * sizeof(uint4);    // 65,536 B -> 2 CTAs/SM
    cudaFuncSetAttribute(k_mma, cudaFuncAttributeMaxDynamicSharedMemorySize,
                         (int)mma_smem);

    const int nb_nodes = (N_NODES + 255) / 256;      // 391
    const int nb_edges = (N_EDGES + 255) / 256;      // 6250
    const int nb_agg   = (N_NODES * 64 + 255) / 256; // 25000
    const int nb_mma   = (N_NODES + 127) / 128;      // 782
    const int nb_wprep = (3 * 4096 + 255) / 256;     // 48

    // idx 0: pack all three W into MMA fragment layout
    k_wprep<<<nb_wprep, 256>>>(W1, Wmu, Wlv);
    // idx 1: degree histogram (g_cnt zeroed by previous replay / static init)
    k_degree<<<nb_edges, 256>>>(dst);
    // idx 2: block scan + dinv
    k_scan1<<<nb_nodes, 256>>>();
    // idx 3 (PROFILED): P1 = X @ W1 (bias/ELU deferred to agg epilogue)
    k_mma<<<nb_mma, 256, mma_smem>>>(x, wf, nullptr, (float*)p_agg,
                                     nullptr, nullptr, nullptr, 0);
    // idx 4-6: finish CSR build
    k_scan2<<<1, 512>>>();
    k_scan3<<<nb_nodes, 256>>>();
    k_fill<<<nb_edges, 256>>>(src, dst);

    // idx 7: h1 = elu(A_norm @ P1 + b1)
    k_agg<<<nb_agg, 256>>>((const float*)p_agg, (float*)p_h1, b1, 1);
    // idx 8: agg2 = A_norm @ h1
    k_agg<<<nb_agg, 256>>>((const float*)p_h1, (float*)p_agg, nullptr, 0);

    // idx 9: mu = agg2 @ Wmu + bmu (scratch + mirrored to out)
    k_mma<<<nb_mma, 256, mma_smem>>>((const float*)p_agg, wf + 4096, bmu,
                                     (float*)p_mu, mu_mirror,
                                     nullptr, nullptr, GF_BIAS);
    // idx 10: lv = agg2 @ Wlv + blv ; z = mu + eps*exp(0.5*lv)
    k_mma<<<nb_mma, 256, mma_smem>>>((const float*)p_agg, wf + 8192, blv,
                                     lv_dst, nullptr,
                                     (const float*)p_mu, out,
                                     GF_BIAS | GF_REP);
}

// round 13
// speedup vs baseline: 2.0535x; 1.9475x over previous
#include <cuda_runtime.h>
#include <cuda_bf16.h>
#include <cstdint>

#define N_NODES 100000
#define N_EDGES 1600000
#define HID     128
#define NH      12800000      // N_NODES * HID
#define NB_SCAN 391           // ceil(N_NODES/256)

// ---------------- scratch (__device__ globals: no runtime allocation) -------
__device__ float g_dinv[N_NODES];
__device__ int   g_cnt[N_NODES];          // zeroed at startup + by k_scan3 each replay
__device__ int   g_rowptr[N_NODES + 1];
__device__ int   g_cursor[N_NODES];
__device__ int2  g_ecc[N_EDGES];          // (src, coef-as-int) interleaved
__device__ int   g_bsum[512];
__device__ int   g_boff[512];
__device__ uint4 g_wfrag[3 * 4096];       // pre-packed bf16 hi/lo MMA fragments
__device__ float g_agg[NH];               // P1 / agg2 buffer
__device__ float g_h1[NH];
__device__ float g_mu[NH];                // fallback if out too small
__device__ float g_lv[NH];

// ---------------- bf16 split helper ------------------------------------------
__device__ __forceinline__ void split2(float2 f, uint32_t& hi, uint32_t& lo) {
    __nv_bfloat162 h = __float22bfloat162_rn(f);
    float2 hf = __bfloat1622float2(h);
    __nv_bfloat162 l = __float22bfloat162_rn(make_float2(f.x - hf.x, f.y - hf.y));
    hi = *reinterpret_cast<uint32_t*>(&h);
    lo = *reinterpret_cast<uint32_t*>(&l);
}

// ---------------- W fragment prepack (one launch, all 3 matrices) ------------
__global__ void k_wprep(const float* __restrict__ W1,
                        const float* __restrict__ Wmu,
                        const float* __restrict__ Wlv) {
    int e = blockIdx.x * 256 + threadIdx.x;
    if (e >= 3 * 4096) return;
    int m = e >> 12;
    const float* W = (m == 0) ? W1 : ((m == 1) ? Wmu : Wlv);
    int f    = e & 4095;
    int lane = f & 31;
    int nn   = (f >> 5) & 15;
    int kk   = f >> 9;
    int t = lane & 3, c = lane >> 2;
    int n  = nn * 8 + c;
    int k0 = kk * 16 + 2 * t;
    float w00 = W[(k0    ) * HID + n], w01 = W[(k0 + 1) * HID + n];
    float w10 = W[(k0 + 8) * HID + n], w11 = W[(k0 + 9) * HID + n];
    uint32_t h0, l0, h1, l1;
    split2(make_float2(w00, w01), h0, l0);
    split2(make_float2(w10, w11), h1, l1);
    g_wfrag[e] = make_uint4(h0, h1, l0, l1);
}

// ---------------- degree ------------------------------------------------------
__global__ void k_degree(const int* __restrict__ dst) {
    int i = blockIdx.x * 256 + threadIdx.x;
    if (i < N_EDGES) atomicAdd(&g_cnt[dst[i]], 1);
}

// ---------------- CSR build ---------------------------------------------------
__global__ void k_scan1() {
    __shared__ int sh[256];
    int tid = threadIdx.x;
    int i = blockIdx.x * 256 + tid;
    int v = (i < N_NODES) ? g_cnt[i] : 0;
    sh[tid] = v;
    __syncthreads();
#pragma unroll
    for (int off = 1; off < 256; off <<= 1) {
        int t = (tid >= off) ? sh[tid - off] : 0;
        __syncthreads();
        sh[tid] += t;
        __syncthreads();
    }
    if (i < N_NODES) {
        g_rowptr[i] = sh[tid] - v;
        g_dinv[i]   = rsqrtf((float)v + 1.0f);
    }
    if (tid == 255) g_bsum[blockIdx.x] = sh[255];
}
__global__ void k_scan2() {
    __shared__ int sh[512];
    int tid = threadIdx.x;
    int v = (tid < NB_SCAN) ? g_bsum[tid] : 0;
    sh[tid] = v;
    __syncthreads();
#pragma unroll
    for (int off = 1; off < 512; off <<= 1) {
        int t = (tid >= off) ? sh[tid - off] : 0;
        __syncthreads();
        sh[tid] += t;
        __syncthreads();
    }
    g_boff[tid] = sh[tid] - v;
    if (tid == 0) g_rowptr[N_NODES] = N_EDGES;
}
__global__ void k_scan3() {
    int i = blockIdx.x * 256 + threadIdx.x;
    if (i < N_NODES) {
        int r = g_rowptr[i] + g_boff[i >> 8];
        g_rowptr[i] = r;
        g_cursor[i] = r;
        g_cnt[i]    = 0;           // ready for next replay
    }
}
__global__ void k_fill(const int* __restrict__ src, const int* __restrict__ dst) {
    int e = blockIdx.x * 256 + threadIdx.x;
    if (e >= N_EDGES) return;
    int d = dst[e], s = src[e];
    int pos = atomicAdd(&g_cursor[d], 1);
    float c = g_dinv[s] * g_dinv[d];
    g_ecc[pos] = make_int2(s, __float_as_int(c));
}

// ---------------- CSR aggregation: out = A_norm @ feat  (+opt bias/ELU) -----
__global__ __launch_bounds__(256) void k_agg(const float* __restrict__ feat,
                                             float* __restrict__ outp,
                                             const float* __restrict__ bias,
                                             int act) {
    int gw   = (blockIdx.x * 256 + threadIdx.x) >> 5;
    int node = gw >> 1;
    int half = gw & 1;
    int lane = threadIdx.x & 31;
    if (node >= N_NODES) return;

    int beg = g_rowptr[node];
    int end = g_rowptr[node + 1];
    float di = g_dinv[node];
    float sc = di * di;

    const float2* fp = (const float2*)feat;
    int off = half * 32 + lane;

    float2 acc = fp[(size_t)node * 64 + off];
    acc.x *= sc; acc.y *= sc;

    int j = beg;
    for (; j + 8 <= end; j += 8) {
        int2 m[8];
#pragma unroll
        for (int q = 0; q < 8; q++) m[q] = g_ecc[j + q];
        float2 v[8];
#pragma unroll
        for (int q = 0; q < 8; q++)
            v[q] = fp[(size_t)m[q].x * 64 + off];
#pragma unroll
        for (int q = 0; q < 8; q++) {
            float c = __int_as_float(m[q].y);
            acc.x = fmaf(c, v[q].x, acc.x);
            acc.y = fmaf(c, v[q].y, acc.y);
        }
    }
    for (; j + 2 <= end; j += 2) {
        int2 m0 = g_ecc[j], m1 = g_ecc[j + 1];
        float2 v0 = fp[(size_t)m0.x * 64 + off];
        float2 v1 = fp[(size_t)m1.x * 64 + off];
        float c0 = __int_as_float(m0.y), c1 = __int_as_float(m1.y);
        acc.x = fmaf(c0, v0.x, acc.x); acc.y = fmaf(c0, v0.y, acc.y);
        acc.x = fmaf(c1, v1.x, acc.x); acc.y = fmaf(c1, v1.y, acc.y);
    }
    if (j < end) {
        int2 m0 = g_ecc[j];
        float2 v0 = fp[(size_t)m0.x * 64 + off];
        float c0 = __int_as_float(m0.y);
        acc.x = fmaf(c0, v0.x, acc.x); acc.y = fmaf(c0, v0.y, acc.y);
    }
    if (bias) {
        float2 b = ((const float2*)bias)[off];
        acc.x += b.x; acc.y += b.y;
    }
    if (act) {
        acc.x = (acc.x > 0.f) ? acc.x : expm1f(acc.x);
        acc.y = (acc.y > 0.f) ? acc.y : expm1f(acc.y);
    }
    ((float2*)outp)[(size_t)node * 64 + off] = acc;
}

// ------- JAX-exact RNG: PARTITIONABLE threefry2x32 + XLA erfinv -------------
__device__ __forceinline__ uint32_t rotl32(uint32_t x, int d) {
    return (x << d) | (x >> (32 - d));
}
__device__ __forceinline__ uint32_t threefry_bits_0_42(uint32_t x0, uint32_t x1) {
    const uint32_t k0 = 0u, k1 = 42u;
    const uint32_t k2 = k0 ^ k1 ^ 0x1BD11BDAu;
    x0 += k0; x1 += k1;
#define TF_RND(r) { x0 += x1; x1 = rotl32(x1, r); x1 ^= x0; }
    TF_RND(13) TF_RND(15) TF_RND(26) TF_RND(6)
    x0 += k1; x1 += k2 + 1u;
    TF_RND(17) TF_RND(29) TF_RND(16) TF_RND(24)
    x0 += k2; x1 += k0 + 2u;
    TF_RND(13) TF_RND(15) TF_RND(26) TF_RND(6)
    x0 += k0; x1 += k1 + 3u;
    TF_RND(17) TF_RND(29) TF_RND(16) TF_RND(24)
    x0 += k1; x1 += k2 + 4u;
    TF_RND(13) TF_RND(15) TF_RND(26) TF_RND(6)
    x0 += k2; x1 += k0 + 5u;
#undef TF_RND
    return x0 ^ x1;
}
__device__ __forceinline__ float erfinv_xla(float x) {
    float w = -log1pf(-x * x);
    float p;
    if (w < 5.0f) {
        w -= 2.5f;
        p = 2.81022636e-08f;
        p = fmaf(p, w, 3.43273939e-07f);
        p = fmaf(p, w, -3.5233877e-06f);
        p = fmaf(p, w, -4.39150654e-06f);
        p = fmaf(p, w, 0.00021858087f);
        p = fmaf(p, w, -0.00125372503f);
        p = fmaf(p, w, -0.00417768164f);
        p = fmaf(p, w, 0.246640727f);
        p = fmaf(p, w, 1.50140941f);
    } else {
        w = sqrtf(w) - 3.0f;
        p = -0.000200214257f;
        p = fmaf(p, w, 0.000100950558f);
        p = fmaf(p, w, 0.00134934322f);
        p = fmaf(p, w, -0.00367342844f);
        p = fmaf(p, w, 0.00573950773f);
        p = fmaf(p, w, -0.0076224613f);
        p = fmaf(p, w, 0.00943887047f);
        p = fmaf(p, w, 1.00167406f);
        p = fmaf(p, w, 2.83297682f);
    }
    return p * x;
}
__device__ __forceinline__ float bits_to_normal(uint32_t bits) {
    float u01 = __uint_as_float((bits >> 9) | 0x3f800000u) - 1.0f;
    const float lo = -0.99999994f;
    float u = fmaf(u01, 2.0f, lo);
    u = fmaxf(u, lo);
    return 1.41421356237f * erfinv_xla(u);
}

// standalone reparam: z = mu + eps * exp(0.5*lv)  (full occupancy, no spills)
__global__ __launch_bounds__(256) void k_reparam(float* __restrict__ z,
                                                 const float* __restrict__ mu,
                                                 const float* __restrict__ lv) {
    int i = blockIdx.x * 256 + threadIdx.x;
    if (i >= NH) return;
    uint32_t bits = threefry_bits_0_42(0u, (uint32_t)i);
    float eps = bits_to_normal(bits);
    z[i] = mu[i] + eps * expf(0.5f * lv[i]);
}

// ---------------- bf16 tensor-core GEMM, 3-term split, prepacked W ----------
// C[M,128] = A[M,128] @ W[128,128] (+bias)(+ELU) — lean epilogue, no spills
#define GF_BIAS 1
#define GF_ELU  2

__device__ __forceinline__ void mma_bf16(float d[4], uint32_t a0, uint32_t a1,
                                         uint32_t a2, uint32_t a3,
                                         uint32_t b0, uint32_t b1) {
    asm volatile("mma.sync.aligned.m16n8k16.row.col.f32.bf16.bf16.f32 "
                 "{%0,%1,%2,%3}, {%4,%5,%6,%7}, {%8,%9}, {%0,%1,%2,%3};"
                 : "+f"(d[0]), "+f"(d[1]), "+f"(d[2]), "+f"(d[3])
                 : "r"(a0), "r"(a1), "r"(a2), "r"(a3), "r"(b0), "r"(b1));
}

__global__ __launch_bounds__(256, 2) void k_mma(const float* __restrict__ A,
                                                const uint4* __restrict__ wf,
                                                const float* __restrict__ bias,
                                                float* __restrict__ C,
                                                int flags) {
    extern __shared__ uint4 sw[];               // 4096 fragment entries (64 KB)
    int tid  = threadIdx.x;
    int warp = tid >> 5;
    int lane = tid & 31;
    int t = lane & 3, g = lane >> 2;

#pragma unroll
    for (int i = 0; i < 16; i++) sw[tid + i * 256] = wf[tid + i * 256];
    __syncthreads();

    int row0 = blockIdx.x << 7;
    int r1 = row0 + warp * 16 + g;
    int r2 = r1 + 8;
    bool v1 = (r1 < N_NODES), v2 = (r2 < N_NODES);
    const float* A1 = A + (size_t)r1 * HID;
    const float* A2 = A + (size_t)r2 * HID;

    float d[16][4];
#pragma unroll
    for (int nn = 0; nn < 16; nn++)
#pragma unroll
        for (int q = 0; q < 4; q++) d[nn][q] = 0.f;

    const float2 z2 = make_float2(0.f, 0.f);

#pragma unroll
    for (int kk = 0; kk < 8; kk++) {
        int kc = kk * 16 + 2 * t;
        float2 f0 = v1 ? *(const float2*)(A1 + kc)     : z2;
        float2 f2 = v1 ? *(const float2*)(A1 + kc + 8) : z2;
        float2 f1 = v2 ? *(const float2*)(A2 + kc)     : z2;
        float2 f3 = v2 ? *(const float2*)(A2 + kc + 8) : z2;
        uint32_t a0h, a0l, a1h, a1l, a2h, a2l, a3h, a3l;
        split2(f0, a0h, a0l);
        split2(f1, a1h, a1l);
        split2(f2, a2h, a2l);
        split2(f3, a3h, a3l);

        const uint4* base = sw + (kk << 9) + lane;
#pragma unroll
        for (int nn = 0; nn < 16; nn++) {
            uint4 b = base[nn << 5];                   // LDS.128, conflict-free
            mma_bf16(d[nn], a0h, a1h, a2h, a3h, b.x, b.y);   // hi*hi
            mma_bf16(d[nn], a0h, a1h, a2h, a3h, b.z, b.w);   // hi*lo
            mma_bf16(d[nn], a0l, a1l, a2l, a3l, b.x, b.y);   // lo*hi
        }
    }

#pragma unroll
    for (int nn = 0; nn < 16; nn++) {
        int col = nn * 8 + 2 * t;
        float bx = 0.f, by = 0.f;
        if (flags & GF_BIAS) {
            float2 b = *(const float2*)(bias + col);
            bx = b.x; by = b.y;
        }
#pragma unroll
        for (int e = 0; e < 2; e++) {
            int r = e ? r2 : r1;
            if (e ? !v2 : !v1) continue;
            float vx = d[nn][2 * e + 0] + bx;
            float vy = d[nn][2 * e + 1] + by;
            if (flags & GF_ELU) {
                vx = (vx > 0.f) ? vx : expm1f(vx);
                vy = (vy > 0.f) ? vy : expm1f(vy);
            }
            *(float2*)(C + (size_t)r * HID + col) = make_float2(vx, vy);
        }
    }
}

// ---------------- launch -----------------------------------------------------
extern "C" void kernel_launch(void* const* d_in, const int* in_sizes, int n_in,
                              void* d_out, int out_size) {
    const float* x   = (const float*)d_in[0];
    const int*   ei  = (const int*)d_in[1];
    const float* W1  = (const float*)d_in[2];
    const float* b1  = (const float*)d_in[3];
    const float* Wmu = (const float*)d_in[4];
    const float* bmu = (const float*)d_in[5];
    const float* Wlv = (const float*)d_in[6];
    const float* blv = (const float*)d_in[7];
    float* out = (float*)d_out;

    const int* src = ei;
    const int* dst = ei + N_EDGES;

    void *p_agg, *p_h1, *p_mu, *p_lv, *p_wf;
    cudaGetSymbolAddress(&p_agg, g_agg);
    cudaGetSymbolAddress(&p_h1,  g_h1);
    cudaGetSymbolAddress(&p_mu,  g_mu);
    cudaGetSymbolAddress(&p_lv,  g_lv);
    cudaGetSymbolAddress(&p_wf,  g_wfrag);
    const uint4* wf = (const uint4*)p_wf;

    int big = (out_size >= 3 * NH);
    float* mu_dst = big ? (out + NH)     : (float*)p_mu;   // write mu directly
    float* lv_dst = big ? (out + 2 * NH) : (float*)p_lv;   // write lv directly

    const size_t mma_smem = 4096 * sizeof(uint4);    // 65,536 B -> 2 CTAs/SM
    cudaFuncSetAttribute(k_mma, cudaFuncAttributeMaxDynamicSharedMemorySize,
                         (int)mma_smem);

    const int nb_nodes = (N_NODES + 255) / 256;      // 391
    const int nb_edges = (N_EDGES + 255) / 256;      // 6250
    const int nb_agg   = (N_NODES * 64 + 255) / 256; // 25000
    const int nb_mma   = (N_NODES + 127) / 128;      // 782
    const int nb_wprep = (3 * 4096 + 255) / 256;     // 48
    const int nb_rep   = (NH + 255) / 256;           // 50000

    // idx 0: pack all three W into MMA fragment layout
    k_wprep<<<nb_wprep, 256>>>(W1, Wmu, Wlv);
    // idx 1: degree histogram
    k_degree<<<nb_edges, 256>>>(dst);
    // idx 2: block scan + dinv
    k_scan1<<<nb_nodes, 256>>>();
    // idx 3 (PROFILED): P1 = X @ W1 (bias/ELU deferred to agg epilogue)
    k_mma<<<nb_mma, 256, mma_smem>>>(x, wf, nullptr, (float*)p_agg, 0);
    // idx 4-6: finish CSR build
    k_scan2<<<1, 512>>>();
    k_scan3<<<nb_nodes, 256>>>();
    k_fill<<<nb_edges, 256>>>(src, dst);

    // idx 7: h1 = elu(A_norm @ P1 + b1)
    k_agg<<<nb_agg, 256>>>((const float*)p_agg, (float*)p_h1, b1, 1);
    // idx 8: agg2 = A_norm @ h1
    k_agg<<<nb_agg, 256>>>((const float*)p_h1, (float*)p_agg, nullptr, 0);

    // idx 9: mu = agg2 @ Wmu + bmu  -> directly into out[NH..2NH)
    k_mma<<<nb_mma, 256, mma_smem>>>((const float*)p_agg, wf + 4096, bmu,
                                     mu_dst, GF_BIAS);
    // idx 10: lv = agg2 @ Wlv + blv -> directly into out[2NH..3NH)
    k_mma<<<nb_mma, 256, mma_smem>>>((const float*)p_agg, wf + 8192, blv,
                                     lv_dst, GF_BIAS);
    // idx 11: z = mu + eps * exp(0.5*lv)  (standalone, full occupancy)
    k_reparam<<<nb_rep, 256>>>(out, mu_dst, lv_dst);
}

// round 16
// speedup vs baseline: 2.1998x; 1.0712x over previous
#include <cuda_runtime.h>
#include <cuda_bf16.h>
#include <cstdint>

#define N_NODES 100000
#define N_EDGES 1600000
#define HID     128
#define NH      12800000      // N_NODES * HID
#define NB_SCAN 391           // ceil(N_NODES/256)

// ---------------- scratch (__device__ globals: no runtime allocation) -------
__device__ float g_dinv[N_NODES];
__device__ int   g_cnt[N_NODES];          // zeroed at startup + by k_scan3 each replay
__device__ int   g_rowptr[N_NODES + 1];
__device__ int   g_cursor[N_NODES];
__device__ int2  g_ecc[N_EDGES];          // (src, coef-as-int) interleaved
__device__ int   g_bsum[512];
__device__ int   g_boff[512];
__device__ uint4 g_wfrag[3 * 4096];       // pre-packed bf16 hi/lo MMA fragments
__device__ float g_agg[NH];               // P1 / agg2 buffer
__device__ float g_h1[NH];
__device__ float g_mu[NH];                // fallback if out too small
__device__ float g_lv[NH];

// ---------------- bf16 split helper ------------------------------------------
__device__ __forceinline__ void split2(float2 f, uint32_t& hi, uint32_t& lo) {
    __nv_bfloat162 h = __float22bfloat162_rn(f);
    float2 hf = __bfloat1622float2(h);
    __nv_bfloat162 l = __float22bfloat162_rn(make_float2(f.x - hf.x, f.y - hf.y));
    hi = *reinterpret_cast<uint32_t*>(&h);
    lo = *reinterpret_cast<uint32_t*>(&l);
}

// ---------------- W fragment prepack (one launch, all 3 matrices) ------------
__global__ void k_wprep(const float* __restrict__ W1,
                        const float* __restrict__ Wmu,
                        const float* __restrict__ Wlv) {
    int e = blockIdx.x * 256 + threadIdx.x;
    if (e >= 3 * 4096) return;
    int m = e >> 12;
    const float* W = (m == 0) ? W1 : ((m == 1) ? Wmu : Wlv);
    int f    = e & 4095;
    int lane = f & 31;
    int nn   = (f >> 5) & 15;
    int kk   = f >> 9;
    int t = lane & 3, c = lane >> 2;
    int n  = nn * 8 + c;
    int k0 = kk * 16 + 2 * t;
    float w00 = W[(k0    ) * HID + n], w01 = W[(k0 + 1) * HID + n];
    float w10 = W[(k0 + 8) * HID + n], w11 = W[(k0 + 9) * HID + n];
    uint32_t h0, l0, h1, l1;
    split2(make_float2(w00, w01), h0, l0);
    split2(make_float2(w10, w11), h1, l1);
    g_wfrag[e] = make_uint4(h0, h1, l0, l1);
}

// ---------------- degree (int4-vectorized: 4 edges/thread) -------------------
__global__ void k_degree(const int4* __restrict__ dst4) {
    int i = blockIdx.x * 256 + threadIdx.x;
    if (i >= N_EDGES / 4) return;
    int4 d = dst4[i];
    atomicAdd(&g_cnt[d.x], 1);
    atomicAdd(&g_cnt[d.y], 1);
    atomicAdd(&g_cnt[d.z], 1);
    atomicAdd(&g_cnt[d.w], 1);
}

// ---------------- CSR build ---------------------------------------------------
__global__ void k_scan1() {
    __shared__ int sh[256];
    int tid = threadIdx.x;
    int i = blockIdx.x * 256 + tid;
    int v = (i < N_NODES) ? g_cnt[i] : 0;
    sh[tid] = v;
    __syncthreads();
#pragma unroll
    for (int off = 1; off < 256; off <<= 1) {
        int t = (tid >= off) ? sh[tid - off] : 0;
        __syncthreads();
        sh[tid] += t;
        __syncthreads();
    }
    if (i < N_NODES) {
        g_rowptr[i] = sh[tid] - v;
        g_dinv[i]   = rsqrtf((float)v + 1.0f);
    }
    if (tid == 255) g_bsum[blockIdx.x] = sh[255];
}
__global__ void k_scan2() {
    __shared__ int sh[512];
    int tid = threadIdx.x;
    int v = (tid < NB_SCAN) ? g_bsum[tid] : 0;
    sh[tid] = v;
    __syncthreads();
#pragma unroll
    for (int off = 1; off < 512; off <<= 1) {
        int t = (tid >= off) ? sh[tid - off] : 0;
        __syncthreads();
        sh[tid] += t;
        __syncthreads();
    }
    g_boff[tid] = sh[tid] - v;
    if (tid == 0) g_rowptr[N_NODES] = N_EDGES;
}
__global__ void k_scan3() {
    int i = blockIdx.x * 256 + threadIdx.x;
    if (i < N_NODES) {
        int r = g_rowptr[i] + g_boff[i >> 8];
        g_rowptr[i] = r;
        g_cursor[i] = r;
        g_cnt[i]    = 0;           // ready for next replay
    }
}
__global__ void k_fill(const int* __restrict__ src, const int* __restrict__ dst) {
    int e = blockIdx.x * 256 + threadIdx.x;
    if (e >= N_EDGES) return;
    int d = dst[e], s = src[e];
    int pos = atomicAdd(&g_cursor[d], 1);
    float c = g_dinv[s] * g_dinv[d];
    g_ecc[pos] = make_int2(s, __float_as_int(c));
}

// ---------------- CSR aggregation: out = A_norm @ feat  (+opt bias/ELU) -----
// 2 warps per node; lane owns float2; groups of 16 edges (MLP=16).
__global__ __launch_bounds__(256) void k_agg(const float* __restrict__ feat,
                                             float* __restrict__ outp,
                                             const float* __restrict__ bias,
                                             int act) {
    int gw   = (blockIdx.x * 256 + threadIdx.x) >> 5;
    int node = gw >> 1;
    int half = gw & 1;
    int lane = threadIdx.x & 31;
    if (node >= N_NODES) return;

    int beg = g_rowptr[node];
    int end = g_rowptr[node + 1];
    float di = g_dinv[node];
    float sc = di * di;

    const float2* fp = (const float2*)feat;
    int off = half * 32 + lane;

    float2 acc = fp[(size_t)node * 64 + off];
    acc.x *= sc; acc.y *= sc;

    int j = beg;
    for (; j + 16 <= end; j += 16) {
        int2 m[16];
#pragma unroll
        for (int q = 0; q < 16; q++) m[q] = g_ecc[j + q];
        float2 v[16];
#pragma unroll
        for (int q = 0; q < 16; q++)
            v[q] = fp[(size_t)m[q].x * 64 + off];
#pragma unroll
        for (int q = 0; q < 16; q++) {
            float c = __int_as_float(m[q].y);
            acc.x = fmaf(c, v[q].x, acc.x);
            acc.y = fmaf(c, v[q].y, acc.y);
        }
    }
    for (; j + 4 <= end; j += 4) {
        int2 m[4];
#pragma unroll
        for (int q = 0; q < 4; q++) m[q] = g_ecc[j + q];
        float2 v[4];
#pragma unroll
        for (int q = 0; q < 4; q++)
            v[q] = fp[(size_t)m[q].x * 64 + off];
#pragma unroll
        for (int q = 0; q < 4; q++) {
            float c = __int_as_float(m[q].y);
            acc.x = fmaf(c, v[q].x, acc.x);
            acc.y = fmaf(c, v[q].y, acc.y);
        }
    }
    for (; j < end; j++) {
        int2 m0 = g_ecc[j];
        float2 v0 = fp[(size_t)m0.x * 64 + off];
        float c0 = __int_as_float(m0.y);
        acc.x = fmaf(c0, v0.x, acc.x); acc.y = fmaf(c0, v0.y, acc.y);
    }
    if (bias) {
        float2 b = ((const float2*)bias)[off];
        acc.x += b.x; acc.y += b.y;
    }
    if (act) {
        acc.x = (acc.x > 0.f) ? acc.x : expm1f(acc.x);
        acc.y = (acc.y > 0.f) ? acc.y : expm1f(acc.y);
    }
    ((float2*)outp)[(size_t)node * 64 + off] = acc;
}

// ------- JAX-exact RNG: PARTITIONABLE threefry2x32 + XLA erfinv -------------
__device__ __forceinline__ uint32_t rotl32(uint32_t x, int d) {
    return (x << d) | (x >> (32 - d));
}
__device__ __forceinline__ uint32_t threefry_bits_0_42(uint32_t x0, uint32_t x1) {
    const uint32_t k0 = 0u, k1 = 42u;
    const uint32_t k2 = k0 ^ k1 ^ 0x1BD11BDAu;
    x0 += k0; x1 += k1;
#define TF_RND(r) { x0 += x1; x1 = rotl32(x1, r); x1 ^= x0; }
    TF_RND(13) TF_RND(15) TF_RND(26) TF_RND(6)
    x0 += k1; x1 += k2 + 1u;
    TF_RND(17) TF_RND(29) TF_RND(16) TF_RND(24)
    x0 += k2; x1 += k0 + 2u;
    TF_RND(13) TF_RND(15) TF_RND(26) TF_RND(6)
    x0 += k0; x1 += k1 + 3u;
    TF_RND(17) TF_RND(29) TF_RND(16) TF_RND(24)
    x0 += k1; x1 += k2 + 4u;
    TF_RND(13) TF_RND(15) TF_RND(26) TF_RND(6)
    x0 += k2; x1 += k0 + 5u;
#undef TF_RND
    return x0 ^ x1;
}
__device__ __forceinline__ float erfinv_xla(float x) {
    float w = -log1pf(-x * x);
    float p;
    if (w < 5.0f) {
        w -= 2.5f;
        p = 2.81022636e-08f;
        p = fmaf(p, w, 3.43273939e-07f);
        p = fmaf(p, w, -3.5233877e-06f);
        p = fmaf(p, w, -4.39150654e-06f);
        p = fmaf(p, w, 0.00021858087f);
        p = fmaf(p, w, -0.00125372503f);
        p = fmaf(p, w, -0.00417768164f);
        p = fmaf(p, w, 0.246640727f);
        p = fmaf(p, w, 1.50140941f);
    } else {
        w = sqrtf(w) - 3.0f;
        p = -0.000200214257f;
        p = fmaf(p, w, 0.000100950558f);
        p = fmaf(p, w, 0.00134934322f);
        p = fmaf(p, w, -0.00367342844f);
        p = fmaf(p, w, 0.00573950773f);
        p = fmaf(p, w, -0.0076224613f);
        p = fmaf(p, w, 0.00943887047f);
        p = fmaf(p, w, 1.00167406f);
        p = fmaf(p, w, 2.83297682f);
    }
    return p * x;
}
__device__ __forceinline__ float bits_to_normal(uint32_t bits) {
    float u01 = __uint_as_float((bits >> 9) | 0x3f800000u) - 1.0f;
    const float lo = -0.99999994f;
    float u = fmaf(u01, 2.0f, lo);
    u = fmaxf(u, lo);
    return 1.41421356237f * erfinv_xla(u);
}

// standalone reparam: z = mu + eps * exp(0.5*lv)
__global__ __launch_bounds__(256) void k_reparam(float* __restrict__ z,
                                                 const float* __restrict__ mu,
                                                 const float* __restrict__ lv) {
    int i = blockIdx.x * 256 + threadIdx.x;
    if (i >= NH) return;
    uint32_t bits = threefry_bits_0_42(0u, (uint32_t)i);
    float eps = bits_to_normal(bits);
    z[i] = mu[i] + eps * expf(0.5f * lv[i]);
}

// ---------------- bf16 tensor-core GEMM, 3-term split, prepacked W ----------
// C[M,128] = A[M,128] @ W[128,128] (+bias)(+ELU) — pipelined A prefetch
#define GF_BIAS 1
#define GF_ELU  2

__device__ __forceinline__ void mma_bf16(float d[4], uint32_t a0, uint32_t a1,
                                         uint32_t a2, uint32_t a3,
                                         uint32_t b0, uint32_t b1) {
    asm volatile("mma.sync.aligned.m16n8k16.row.col.f32.bf16.bf16.f32 "
                 "{%0,%1,%2,%3}, {%4,%5,%6,%7}, {%8,%9}, {%0,%1,%2,%3};"
                 : "+f"(d[0]), "+f"(d[1]), "+f"(d[2]), "+f"(d[3])
                 : "r"(a0), "r"(a1), "r"(a2), "r"(a3), "r"(b0), "r"(b1));
}

__global__ __launch_bounds__(256, 2) void k_mma(const float* __restrict__ A,
                                                const uint4* __restrict__ wf,
                                                const float* __restrict__ bias,
                                                float* __restrict__ C,
                                                int flags) {
    extern __shared__ uint4 sw[];               // 4096 fragment entries (64 KB)
    int tid  = threadIdx.x;
    int warp = tid >> 5;
    int lane = tid & 31;
    int t = lane & 3, g = lane >> 2;

#pragma unroll
    for (int i = 0; i < 16; i++) sw[tid + i * 256] = wf[tid + i * 256];
    __syncthreads();

    int row0 = blockIdx.x << 7;
    int r1 = row0 + warp * 16 + g;
    int r2 = r1 + 8;
    bool v1 = (r1 < N_NODES), v2 = (r2 < N_NODES);
    // clamped pointers: unconditional loads, garbage rows never stored
    const float* A1 = A + (size_t)(v1 ? r1 : N_NODES - 1) * HID;
    const float* A2 = A + (size_t)(v2 ? r2 : N_NODES - 1) * HID;

    float d[16][4];
#pragma unroll
    for (int nn = 0; nn < 16; nn++)
#pragma unroll
        for (int q = 0; q < 4; q++) d[nn][q] = 0.f;

    int kc0 = 2 * t;
    float2 f0 = *(const float2*)(A1 + kc0);
    float2 f1 = *(const float2*)(A2 + kc0);
    float2 f2 = *(const float2*)(A1 + kc0 + 8);
    float2 f3 = *(const float2*)(A2 + kc0 + 8);

#pragma unroll
    for (int kk = 0; kk < 8; kk++) {
        uint32_t a0h, a0l, a1h, a1l, a2h, a2l, a3h, a3l;
        split2(f0, a0h, a0l);
        split2(f1, a1h, a1l);
        split2(f2, a2h, a2l);
        split2(f3, a3h, a3l);

        if (kk < 7) {                       // prefetch next kk during MMA burst
            int kc = (kk + 1) * 16 + 2 * t;
            f0 = *(const float2*)(A1 + kc);
            f1 = *(const float2*)(A2 + kc);
            f2 = *(const float2*)(A1 + kc + 8);
            f3 = *(const float2*)(A2 + kc + 8);
        }

        const uint4* base = sw + (kk << 9) + lane;
#pragma unroll
        for (int nn = 0; nn < 16; nn++) {
            uint4 b = base[nn << 5];                   // LDS.128, conflict-free
            mma_bf16(d[nn], a0h, a1h, a2h, a3h, b.x, b.y);   // hi*hi
            mma_bf16(d[nn], a0h, a1h, a2h, a3h, b.z, b.w);   // hi*lo
            mma_bf16(d[nn], a0l, a1l, a2l, a3l, b.x, b.y);   // lo*hi
        }
    }

#pragma unroll
    for (int nn = 0; nn < 16; nn++) {
        int col = nn * 8 + 2 * t;
        float bx = 0.f, by = 0.f;
        if (flags & GF_BIAS) {
            float2 b = *(const float2*)(bias + col);
            bx = b.x; by = b.y;
        }
#pragma unroll
        for (int e = 0; e < 2; e++) {
            int r = e ? r2 : r1;
            if (e ? !v2 : !v1) continue;
            float vx = d[nn][2 * e + 0] + bx;
            float vy = d[nn][2 * e + 1] + by;
            if (flags & GF_ELU) {
                vx = (vx > 0.f) ? vx : expm1f(vx);
                vy = (vy > 0.f) ? vy : expm1f(vy);
            }
            *(float2*)(C + (size_t)r * HID + col) = make_float2(vx, vy);
        }
    }
}

// ---------------- launch -----------------------------------------------------
extern "C" void kernel_launch(void* const* d_in, const int* in_sizes, int n_in,
                              void* d_out, int out_size) {
    const float* x   = (const float*)d_in[0];
    const int*   ei  = (const int*)d_in[1];
    const float* W1  = (const float*)d_in[2];
    const float* b1  = (const float*)d_in[3];
    const float* Wmu = (const float*)d_in[4];
    const float* bmu = (const float*)d_in[5];
    const float* Wlv = (const float*)d_in[6];
    const float* blv = (const float*)d_in[7];
    float* out = (float*)d_out;

    const int* src = ei;
    const int* dst = ei + N_EDGES;

    void *p_agg, *p_h1, *p_mu, *p_lv, *p_wf;
    cudaGetSymbolAddress(&p_agg, g_agg);
    cudaGetSymbolAddress(&p_h1,  g_h1);
    cudaGetSymbolAddress(&p_mu,  g_mu);
    cudaGetSymbolAddress(&p_lv,  g_lv);
    cudaGetSymbolAddress(&p_wf,  g_wfrag);
    const uint4* wf = (const uint4*)p_wf;

    int big = (out_size >= 3 * NH);
    float* mu_dst = big ? (out + NH)     : (float*)p_mu;
    float* lv_dst = big ? (out + 2 * NH) : (float*)p_lv;

    const size_t mma_smem = 4096 * sizeof(uint4);    // 65,536 B -> 2 CTAs/SM
    cudaFuncSetAttribute(k_mma, cudaFuncAttributeMaxDynamicSharedMemorySize,
                         (int)mma_smem);

    const int nb_nodes = (N_NODES + 255) / 256;      // 391
    const int nb_edges = (N_EDGES + 255) / 256;      // 6250
    const int nb_deg4  = (N_EDGES / 4 + 255) / 256;  // 1563
    const int nb_agg   = (N_NODES * 64 + 255) / 256; // 25000
    const int nb_mma   = (N_NODES + 127) / 128;      // 782
    const int nb_wprep = (3 * 4096 + 255) / 256;     // 48
    const int nb_rep   = (NH + 255) / 256;           // 50000

    // idx 0: pack all three W into MMA fragment layout
    k_wprep<<<nb_wprep, 256>>>(W1, Wmu, Wlv);
    // idx 1: degree histogram (vectorized)
    k_degree<<<nb_deg4, 256>>>((const int4*)dst);
    // idx 2: block scan + dinv
    k_scan1<<<nb_nodes, 256>>>();
    // idx 3 (PROFILED): P1 = X @ W1 (bias/ELU deferred to agg epilogue)
    k_mma<<<nb_mma, 256, mma_smem>>>(x, wf, nullptr, (float*)p_agg, 0);
    // idx 4-6: finish CSR build
    k_scan2<<<1, 512>>>();
    k_scan3<<<nb_nodes, 256>>>();
    k_fill<<<nb_edges, 256>>>(src, dst);

    // idx 7: h1 = elu(A_norm @ P1 + b1)
    k_agg<<<nb_agg, 256>>>((const float*)p_agg, (float*)p_h1, b1, 1);
    // idx 8: agg2 = A_norm @ h1
    k_agg<<<nb_agg, 256>>>((const float*)p_h1, (float*)p_agg, nullptr, 0);

    // idx 9: mu = agg2 @ Wmu + bmu  -> directly into out[NH..2NH)
    k_mma<<<nb_mma, 256, mma_smem>>>((const float*)p_agg, wf + 4096, bmu,
                                     mu_dst, GF_BIAS);
    // idx 10: lv = agg2 @ Wlv + blv -> directly into out[2NH..3NH)
    k_mma<<<nb_mma, 256, mma_smem>>>((const float*)p_agg, wf + 8192, blv,
                                     lv_dst, GF_BIAS);
    // idx 11: z = mu + eps * exp(0.5*lv)
    k_reparam<<<nb_rep, 256>>>(out, mu_dst, lv_dst);
}